// round 13
// baseline (speedup 1.0000x reference)
#include <cuda_runtime.h>
#include <cuda_fp16.h>
#include <cstdint>

// ===========================================================================
// GroupedLinear: ragged GEMM. G=16, K=2048, N=2048, T=16384 (uniform groups).
// fp16 mma.sync.m16n8k16. R11: BK=64 (half the barriers/cp_waits of R10),
// 16 warps (4M x 4N, warp 64x32), fused fp32->fp16 W load path.
// ===========================================================================
#define G_ 16
#define K_ 2048
#define N_ 2048
#define T_ 16384

#define BM 256
#define BN 128
#define BK 64
#define NASTAGE 3                   // A: cp.async stages (fp16)
#define NBSTAGE 2                   // B: LDG+cvt+STS stages (fp16 in smem)
#define KITERS (K_ / BK)            // 32
#define NTHREADS 512                // 16 warps: 4 along M, 4 along N

// smem row pitches (halves); 144B / 272B rows are odd multiples of 16B ->
// ldmatrix phase-conflict-free
#define APITCH (BK + 8)             // 72 halves = 144 B
#define BPITCH (BN + 8)             // 136 halves = 272 B
#define ASTAGE_B (BM * APITCH * 2)  // 36864 B
#define BSTAGE_B (BK * BPITCH * 2)  // 17408 B
#define SMEM_TOTAL (NASTAGE * ASTAGE_B + NBSTAGE * BSTAGE_B)   // 145408 B

// fp16 scratch for A only (W is converted in-GEMM)
__device__ __align__(16) __half g_Ah[(size_t)T_ * K_];          // 67 MB

// ===========================================================================
// helpers
// ===========================================================================
__device__ __forceinline__ uint32_t smem_u32(const void* p) {
    uint32_t a;
    asm("{ .reg .u64 t; cvta.to.shared.u64 t, %1; cvt.u32.u64 %0, t; }"
        : "=r"(a) : "l"(p));
    return a;
}

__device__ __forceinline__ void cp_async16(uint32_t saddr, const void* gaddr) {
    asm volatile("cp.async.cg.shared.global [%0], [%1], 16;"
                 :: "r"(saddr), "l"(gaddr) : "memory");
}
__device__ __forceinline__ void cp_commit() {
    asm volatile("cp.async.commit_group;" ::: "memory");
}
template <int N>
__device__ __forceinline__ void cp_wait() {
    asm volatile("cp.async.wait_group %0;" :: "n"(N) : "memory");
}

__device__ __forceinline__ void ldsm_x4(uint32_t* r, uint32_t saddr) {
    asm volatile("ldmatrix.sync.aligned.m8n8.x4.shared.b16 {%0,%1,%2,%3}, [%4];"
                 : "=r"(r[0]), "=r"(r[1]), "=r"(r[2]), "=r"(r[3]) : "r"(saddr));
}
__device__ __forceinline__ void ldsm_x4_t(uint32_t* r, uint32_t saddr) {
    asm volatile("ldmatrix.sync.aligned.m8n8.x4.trans.shared.b16 {%0,%1,%2,%3}, [%4];"
                 : "=r"(r[0]), "=r"(r[1]), "=r"(r[2]), "=r"(r[3]) : "r"(saddr));
}

__device__ __forceinline__ void mma16816(float* c, const uint32_t* a, const uint32_t* b) {
    asm volatile(
        "mma.sync.aligned.m16n8k16.row.col.f32.f16.f16.f32 "
        "{%0,%1,%2,%3}, {%4,%5,%6,%7}, {%8,%9}, {%0,%1,%2,%3};"
        : "+f"(c[0]), "+f"(c[1]), "+f"(c[2]), "+f"(c[3])
        : "r"(a[0]), "r"(a[1]), "r"(a[2]), "r"(a[3]), "r"(b[0]), "r"(b[1]));
}

__device__ __forceinline__ void sts_w64(uint32_t saddr, float4 v) {
    __half2 h0 = __floats2half2_rn(v.x, v.y);
    __half2 h1 = __floats2half2_rn(v.z, v.w);
    uint32_t u0 = *reinterpret_cast<uint32_t*>(&h0);
    uint32_t u1 = *reinterpret_cast<uint32_t*>(&h1);
    asm volatile("st.shared.v2.b32 [%0], {%1, %2};"
                 :: "r"(saddr), "r"(u0), "r"(u1) : "memory");
}

// ===========================================================================
// Kernel 1: A fp32 -> fp16 elementwise
// ===========================================================================
__global__ void __launch_bounds__(256) conv_half_kernel(
    const float4* __restrict__ in, uint2* __restrict__ out, int n4)
{
    int i = blockIdx.x * blockDim.x + threadIdx.x;
    if (i < n4) {
        float4 v = in[i];
        __half2 lo = __floats2half2_rn(v.x, v.y);
        __half2 hi = __floats2half2_rn(v.z, v.w);
        uint2 r;
        r.x = *reinterpret_cast<uint32_t*>(&lo);
        r.y = *reinterpret_cast<uint32_t*>(&hi);
        out[i] = r;
    }
}

// ===========================================================================
// Kernel 2: grouped GEMM, BK=64 mainloop.
//   A: 3-stage cp.async ring (fp16 scratch), prefetch distance 2, wait<1>.
//   B: W fp32 LDG -> cvt -> STS fp16, 2-stage ring, prefetch distance 2.
//   One __syncthreads per 64-k iteration (32 total).
// ===========================================================================
__global__ void __launch_bounds__(NTHREADS, 1) gemm_hmma_kernel(
    const __half* __restrict__ Ah,
    const float* __restrict__ W,            // original fp32 weights [G,K,N]
    const int* __restrict__ offsets,
    const int* __restrict__ tokens_per_expert,
    float* __restrict__ out)
{
    extern __shared__ char smem[];
    const uint32_t sbase  = smem_u32(smem);
    const uint32_t sBbase = sbase + NASTAGE * ASTAGE_B;

    const int tid  = threadIdx.x;
    const int wid  = tid >> 5;
    const int lane = tid & 31;

    const int nt = blockIdx.x;                 // N tile
    const int mt = blockIdx.y;                 // M tile within group
    const int g  = blockIdx.z;                 // group

    const int row0      = offsets[g] + mt * BM;
    const int rows_left = tokens_per_expert[g] - mt * BM;

    const int wm = wid & 3;                    // 4 warps along M (64 rows each)
    const int wn = wid >> 2;                   // 4 warps along N (32 cols each)

    const float4* Wg4 = reinterpret_cast<const float4*>(
        W + (size_t)g * K_ * N_) + (size_t)nt * (BN / 4);

    // ------- A cooperative cp.async mapping -------
    // A tile: 256 rows x 8 chunks(16B) = 2048 chunks; 4/thread
    const int a_row0 = tid >> 3, a_ch = tid & 7;

    auto load_a_stage = [&](int s, int kt) {
        const int k0 = kt * BK;
        const uint32_t sa = sbase + s * ASTAGE_B;
#pragma unroll
        for (int p = 0; p < 4; p++) {
            int r = a_row0 + p * 64;
            int grow = row0 + r;
            if (grow > T_ - 1) grow = T_ - 1;          // ragged safety clamp
            cp_async16(sa + r * (APITCH * 2) + a_ch * 16,
                       Ah + (size_t)grow * K_ + k0 + a_ch * 8);
        }
    };

    // ------- W fp32 load / fp16 store mapping -------
    // B tile: 64 rows x 32 float4-chunks = 2048 chunks; 4/thread
    const int w_row = tid >> 5;                // 0..15 (warp-uniform)
    const int w_c4  = tid & 31;                // float4 column chunk

    auto ldg_w = [&](int kt, float4* wbuf) {
#pragma unroll
        for (int p = 0; p < 4; p++) {
            int r = w_row + p * 16;
            wbuf[p] = __ldg(&Wg4[(size_t)(kt * BK + r) * (N_ / 4) + w_c4]);
        }
    };
    auto sts_w = [&](int s, const float4* wbuf) {
        const uint32_t sB = sBbase + s * BSTAGE_B;
#pragma unroll
        for (int p = 0; p < 4; p++) {
            int r = w_row + p * 16;
            sts_w64(sB + r * (BPITCH * 2) + w_c4 * 8, wbuf[p]);
        }
    };

    float acc[4][4][4];
#pragma unroll
    for (int i = 0; i < 4; i++)
#pragma unroll
        for (int j = 0; j < 4; j++)
#pragma unroll
            for (int v = 0; v < 4; v++) acc[i][j][v] = 0.0f;

    // ------- prologue -------
    float4 wbuf[4];
    ldg_w(0, wbuf);
    sts_w(0, wbuf);                 // B stage 0 = iter 0 (visible after 1st barrier)
    ldg_w(1, wbuf);                 // in-register data for iter 1

    load_a_stage(0, 0); cp_commit();
    load_a_stage(1, 1); cp_commit();

    // ldmatrix per-lane offsets
    const int lr   = lane & 15;                // row within 16
    const int lcol = (lane >> 4) * 8;          // 8-half column offset

    for (int kt = 0; kt < KITERS; kt++) {
        cp_wait<1>();              // A stage kt resident
        __syncthreads();           // A kt + B kt visible; ring reuse safe

        // B pipeline: store iter kt+1 (from regs), prefetch kt+2 (to regs)
        if (kt + 1 < KITERS) sts_w((kt + 1) % NBSTAGE, wbuf);
        if (kt + 2 < KITERS) ldg_w(kt + 2, wbuf);

        // A pipeline: prefetch stage kt+2
        if (kt + 2 < KITERS) load_a_stage((kt + 2) % NASTAGE, kt + 2);
        cp_commit();

        const uint32_t sa  = sbase  + (kt % NASTAGE) * ASTAGE_B;
        const uint32_t sbB = sBbase + (kt % NBSTAGE) * BSTAGE_B;

#pragma unroll
        for (int kc = 0; kc < 4; kc++) {       // four k16 chunks in BK=64
            uint32_t afr[4][4];
#pragma unroll
            for (int mi = 0; mi < 4; mi++) {
                int m = wm * 64 + mi * 16 + lr;
                ldsm_x4(afr[mi], sa + m * (APITCH * 2) + (kc * 16 + lcol) * 2);
            }
            uint32_t bfr[2][4];
#pragma unroll
            for (int nc = 0; nc < 2; nc++) {   // two n16 chunks in warp's 32 cols
                int k = kc * 16 + lr;
                int n = wn * 32 + nc * 16 + lcol;
                ldsm_x4_t(bfr[nc], sbB + k * (BPITCH * 2) + n * 2);
            }
#pragma unroll
            for (int mi = 0; mi < 4; mi++)
#pragma unroll
                for (int ni = 0; ni < 4; ni++) {
                    const uint32_t* b = &bfr[ni >> 1][(ni & 1) * 2];
                    mma16816(acc[mi][ni], afr[mi], b);
                }
        }
    }

    // ------- epilogue: direct fp32 stores -------
    const int groupID = lane >> 2;
    const int tin     = lane & 3;
#pragma unroll
    for (int mi = 0; mi < 4; mi++) {
#pragma unroll
        for (int half = 0; half < 2; half++) {
            int mrow = wm * 64 + mi * 16 + groupID + half * 8;
            if (mrow < rows_left) {
                size_t obase = (size_t)(row0 + mrow) * N_ + nt * BN + wn * 32;
#pragma unroll
                for (int ni = 0; ni < 4; ni++) {
                    float2 v;
                    v.x = acc[mi][ni][half * 2 + 0];
                    v.y = acc[mi][ni][half * 2 + 1];
                    *reinterpret_cast<float2*>(out + obase + ni * 8 + tin * 2) = v;
                }
            }
        }
    }
}

// ===========================================================================
// Host launch
// ===========================================================================
extern "C" void kernel_launch(void* const* d_in, const int* in_sizes, int n_in,
                              void* d_out, int out_size)
{
    const float* hidden  = (const float*)d_in[0];
    const float* weight  = (const float*)d_in[1];
    const int*   offsets = (const int*)d_in[2];
    // d_in[3] = blockscale_offsets (unused by reference math)
    const int*   tokens  = (const int*)d_in[4];
    float*       out     = (float*)d_out;

    void* ah_ptr = nullptr;
    cudaGetSymbolAddress(&ah_ptr, g_Ah);

    {   // A -> fp16 (W is converted inside the GEMM)
        int n4 = (T_ * K_) / 4;
        conv_half_kernel<<<(n4 + 255) / 256, 256>>>(
            (const float4*)hidden, (uint2*)ah_ptr, n4);
    }

    cudaFuncSetAttribute(gemm_hmma_kernel,
                         cudaFuncAttributeMaxDynamicSharedMemorySize, SMEM_TOTAL);

    dim3 grid(N_ / BN, (T_ / G_) / BM, G_);    // (16, 4, 16)
    gemm_hmma_kernel<<<grid, NTHREADS, SMEM_TOTAL>>>(
        (const __half*)ah_ptr, weight, offsets, tokens, out);
}

// round 14
// speedup vs baseline: 1.0144x; 1.0144x over previous
#include <cuda_runtime.h>
#include <cuda_fp16.h>
#include <cstdint>

// ===========================================================================
// GroupedLinear: ragged GEMM. G=16, K=2048, N=2048, T=16384 (uniform groups).
// fp16 mma.sync.m16n8k16. R13: 2 CTAs/SM for barrier overlap — BM=128 BN=128
// BK=32, 8 warps (warp 64x32), fused fp32->fp16 W load path.
// ===========================================================================
#define G_ 16
#define K_ 2048
#define N_ 2048
#define T_ 16384

#define BM 128
#define BN 128
#define BK 32
#define NASTAGE 4                   // A: cp.async stages (fp16)
#define NBSTAGE 3                   // B: LDG+cvt+STS stages (fp16 in smem)
#define KITERS (K_ / BK)            // 64
#define NTHREADS 256                // 8 warps: 2 along M, 4 along N

// smem row pitches (halves); 80B / 272B rows are odd multiples of 16B ->
// ldmatrix phase-conflict-free
#define APITCH (BK + 8)             // 40 halves = 80 B
#define BPITCH (BN + 8)             // 136 halves = 272 B
#define ASTAGE_B (BM * APITCH * 2)  // 10240 B
#define BSTAGE_B (BK * BPITCH * 2)  // 8704 B
#define SMEM_TOTAL (NASTAGE * ASTAGE_B + NBSTAGE * BSTAGE_B)   // 67072 B -> 2 CTAs/SM

// fp16 scratch for A only (W is converted in-GEMM)
__device__ __align__(16) __half g_Ah[(size_t)T_ * K_];          // 67 MB

// ===========================================================================
// helpers
// ===========================================================================
__device__ __forceinline__ uint32_t smem_u32(const void* p) {
    uint32_t a;
    asm("{ .reg .u64 t; cvta.to.shared.u64 t, %1; cvt.u32.u64 %0, t; }"
        : "=r"(a) : "l"(p));
    return a;
}

__device__ __forceinline__ void cp_async16(uint32_t saddr, const void* gaddr) {
    asm volatile("cp.async.cg.shared.global [%0], [%1], 16;"
                 :: "r"(saddr), "l"(gaddr) : "memory");
}
__device__ __forceinline__ void cp_commit() {
    asm volatile("cp.async.commit_group;" ::: "memory");
}
template <int N>
__device__ __forceinline__ void cp_wait() {
    asm volatile("cp.async.wait_group %0;" :: "n"(N) : "memory");
}

__device__ __forceinline__ void ldsm_x4(uint32_t* r, uint32_t saddr) {
    asm volatile("ldmatrix.sync.aligned.m8n8.x4.shared.b16 {%0,%1,%2,%3}, [%4];"
                 : "=r"(r[0]), "=r"(r[1]), "=r"(r[2]), "=r"(r[3]) : "r"(saddr));
}
__device__ __forceinline__ void ldsm_x4_t(uint32_t* r, uint32_t saddr) {
    asm volatile("ldmatrix.sync.aligned.m8n8.x4.trans.shared.b16 {%0,%1,%2,%3}, [%4];"
                 : "=r"(r[0]), "=r"(r[1]), "=r"(r[2]), "=r"(r[3]) : "r"(saddr));
}

__device__ __forceinline__ void mma16816(float* c, const uint32_t* a, const uint32_t* b) {
    asm volatile(
        "mma.sync.aligned.m16n8k16.row.col.f32.f16.f16.f32 "
        "{%0,%1,%2,%3}, {%4,%5,%6,%7}, {%8,%9}, {%0,%1,%2,%3};"
        : "+f"(c[0]), "+f"(c[1]), "+f"(c[2]), "+f"(c[3])
        : "r"(a[0]), "r"(a[1]), "r"(a[2]), "r"(a[3]), "r"(b[0]), "r"(b[1]));
}

__device__ __forceinline__ void sts_w64(uint32_t saddr, float4 v) {
    __half2 h0 = __floats2half2_rn(v.x, v.y);
    __half2 h1 = __floats2half2_rn(v.z, v.w);
    uint32_t u0 = *reinterpret_cast<uint32_t*>(&h0);
    uint32_t u1 = *reinterpret_cast<uint32_t*>(&h1);
    asm volatile("st.shared.v2.b32 [%0], {%1, %2};"
                 :: "r"(saddr), "r"(u0), "r"(u1) : "memory");
}

// ===========================================================================
// Kernel 1: A fp32 -> fp16 elementwise
// ===========================================================================
__global__ void __launch_bounds__(256) conv_half_kernel(
    const float4* __restrict__ in, uint2* __restrict__ out, int n4)
{
    int i = blockIdx.x * blockDim.x + threadIdx.x;
    if (i < n4) {
        float4 v = in[i];
        __half2 lo = __floats2half2_rn(v.x, v.y);
        __half2 hi = __floats2half2_rn(v.z, v.w);
        uint2 r;
        r.x = *reinterpret_cast<uint32_t*>(&lo);
        r.y = *reinterpret_cast<uint32_t*>(&hi);
        out[i] = r;
    }
}

// ===========================================================================
// Kernel 2: grouped GEMM, 2 CTAs/SM.
//   A: 4-stage cp.async ring (fp16 scratch), prefetch distance 3, wait<2>.
//   B: W fp32 LDG -> cvt -> STS fp16, 3-stage ring, prefetch distance 2.
//   out[row, n] = sum_k A[row, k] * W[g, k, n]
// ===========================================================================
__global__ void __launch_bounds__(NTHREADS, 2) gemm_hmma_kernel(
    const __half* __restrict__ Ah,
    const float* __restrict__ W,            // original fp32 weights [G,K,N]
    const int* __restrict__ offsets,
    const int* __restrict__ tokens_per_expert,
    float* __restrict__ out)
{
    extern __shared__ char smem[];
    const uint32_t sbase  = smem_u32(smem);
    const uint32_t sBbase = sbase + NASTAGE * ASTAGE_B;

    const int tid  = threadIdx.x;
    const int wid  = tid >> 5;
    const int lane = tid & 31;

    const int nt = blockIdx.x;                 // N tile
    const int mt = blockIdx.y;                 // M tile within group
    const int g  = blockIdx.z;                 // group

    const int row0      = offsets[g] + mt * BM;
    const int rows_left = tokens_per_expert[g] - mt * BM;

    const int wm = wid & 1;                    // 2 warps along M (64 rows each)
    const int wn = wid >> 1;                   // 4 warps along N (32 cols each)

    const float4* Wg4 = reinterpret_cast<const float4*>(
        W + (size_t)g * K_ * N_) + (size_t)nt * (BN / 4);

    // ------- A cooperative cp.async mapping -------
    // A tile: 128 rows x 4 chunks(16B) = 512 chunks; 2/thread
    const int a_row0 = tid >> 2, a_ch = tid & 3;

    auto load_a_stage = [&](int s, int kt) {
        const int k0 = kt * BK;
        const uint32_t sa = sbase + s * ASTAGE_B;
#pragma unroll
        for (int p = 0; p < 2; p++) {
            int r = a_row0 + p * 64;
            int grow = row0 + r;
            if (grow > T_ - 1) grow = T_ - 1;          // ragged safety clamp
            cp_async16(sa + r * (APITCH * 2) + a_ch * 16,
                       Ah + (size_t)grow * K_ + k0 + a_ch * 8);
        }
    };

    // ------- W fp32 load / fp16 store mapping -------
    // B tile: 32 rows x 32 float4-chunks = 1024 chunks; 4/thread
    const int w_row = tid >> 5;                // 0..7 (warp-uniform)
    const int w_c4  = tid & 31;                // float4 column chunk

    auto ldg_w = [&](int kt, float4* wbuf) {
#pragma unroll
        for (int p = 0; p < 4; p++) {
            int r = w_row + p * 8;
            wbuf[p] = __ldg(&Wg4[(size_t)(kt * BK + r) * (N_ / 4) + w_c4]);
        }
    };
    auto sts_w = [&](int s, const float4* wbuf) {
        const uint32_t sB = sBbase + s * BSTAGE_B;
#pragma unroll
        for (int p = 0; p < 4; p++) {
            int r = w_row + p * 8;
            sts_w64(sB + r * (BPITCH * 2) + w_c4 * 8, wbuf[p]);
        }
    };

    float acc[4][4][4];
#pragma unroll
    for (int i = 0; i < 4; i++)
#pragma unroll
        for (int j = 0; j < 4; j++)
#pragma unroll
            for (int v = 0; v < 4; v++) acc[i][j][v] = 0.0f;

    // ------- prologue -------
    float4 wbuf[4];
    ldg_w(0, wbuf);
    sts_w(0, wbuf);                 // B stage 0 = iter 0 (visible after 1st barrier)
    ldg_w(1, wbuf);                 // in-register data for iter 1

    load_a_stage(0, 0); cp_commit();
    load_a_stage(1, 1); cp_commit();
    load_a_stage(2, 2); cp_commit();

    // ldmatrix per-lane offsets
    const int lr   = lane & 15;                // row within 16
    const int lcol = (lane >> 4) * 8;          // 8-half column offset

    for (int kt = 0; kt < KITERS; kt++) {
        cp_wait<2>();              // A stage kt resident
        __syncthreads();           // A kt + B kt visible; ring reuse safe

        // B pipeline: store iter kt+1 (from regs), prefetch kt+2 (to regs)
        if (kt + 1 < KITERS) sts_w((kt + 1) % NBSTAGE, wbuf);
        if (kt + 2 < KITERS) ldg_w(kt + 2, wbuf);

        // A pipeline: prefetch stage kt+3
        if (kt + 3 < KITERS) load_a_stage((kt + 3) & (NASTAGE - 1), kt + 3);
        cp_commit();

        const uint32_t sa  = sbase  + (kt & (NASTAGE - 1)) * ASTAGE_B;
        const uint32_t sbB = sBbase + (kt % NBSTAGE) * BSTAGE_B;

#pragma unroll
        for (int kc = 0; kc < 2; kc++) {       // two k16 chunks in BK=32
            uint32_t afr[4][4];
#pragma unroll
            for (int mi = 0; mi < 4; mi++) {
                int m = wm * 64 + mi * 16 + lr;
                ldsm_x4(afr[mi], sa + m * (APITCH * 2) + (kc * 16 + lcol) * 2);
            }
            uint32_t bfr[2][4];
#pragma unroll
            for (int nc = 0; nc < 2; nc++) {   // two n16 chunks in warp's 32 cols
                int k = kc * 16 + lr;
                int n = wn * 32 + nc * 16 + lcol;
                ldsm_x4_t(bfr[nc], sbB + k * (BPITCH * 2) + n * 2);
            }
#pragma unroll
            for (int mi = 0; mi < 4; mi++)
#pragma unroll
                for (int ni = 0; ni < 4; ni++) {
                    const uint32_t* b = &bfr[ni >> 1][(ni & 1) * 2];
                    mma16816(acc[mi][ni], afr[mi], b);
                }
        }
    }

    // ------- epilogue: direct fp32 stores -------
    const int groupID = lane >> 2;
    const int tin     = lane & 3;
#pragma unroll
    for (int mi = 0; mi < 4; mi++) {
#pragma unroll
        for (int half = 0; half < 2; half++) {
            int mrow = wm * 64 + mi * 16 + groupID + half * 8;
            if (mrow < rows_left) {
                size_t obase = (size_t)(row0 + mrow) * N_ + nt * BN + wn * 32;
#pragma unroll
                for (int ni = 0; ni < 4; ni++) {
                    float2 v;
                    v.x = acc[mi][ni][half * 2 + 0];
                    v.y = acc[mi][ni][half * 2 + 1];
                    *reinterpret_cast<float2*>(out + obase + ni * 8 + tin * 2) = v;
                }
            }
        }
    }
}

// ===========================================================================
// Host launch
// ===========================================================================
extern "C" void kernel_launch(void* const* d_in, const int* in_sizes, int n_in,
                              void* d_out, int out_size)
{
    const float* hidden  = (const float*)d_in[0];
    const float* weight  = (const float*)d_in[1];
    const int*   offsets = (const int*)d_in[2];
    // d_in[3] = blockscale_offsets (unused by reference math)
    const int*   tokens  = (const int*)d_in[4];
    float*       out     = (float*)d_out;

    void* ah_ptr = nullptr;
    cudaGetSymbolAddress(&ah_ptr, g_Ah);

    {   // A -> fp16 (W is converted inside the GEMM)
        int n4 = (T_ * K_) / 4;
        conv_half_kernel<<<(n4 + 255) / 256, 256>>>(
            (const float4*)hidden, (uint2*)ah_ptr, n4);
    }

    cudaFuncSetAttribute(gemm_hmma_kernel,
                         cudaFuncAttributeMaxDynamicSharedMemorySize, SMEM_TOTAL);

    dim3 grid(N_ / BN, (T_ / G_) / BM, G_);    // (16, 8, 16)
    gemm_hmma_kernel<<<grid, NTHREADS, SMEM_TOTAL>>>(
        (const __half*)ah_ptr, weight, offsets, tokens, out);
}